// round 3
// baseline (speedup 1.0000x reference)
#include <cuda_runtime.h>

// ---------------------------------------------------------------------------
// 3-layer GCN. edge_index is int32.
// Strategy: CSR build (histogram -> scan -> bucket) once per launch, then
// per layer: reg-blocked 8x8 GEMM (epilogue = h*dinv + bias) + CSR gather
// (no float atomics; everything L2-resident).
// ---------------------------------------------------------------------------

#define NN 50000
#define EE 640000

__device__ float g_h[NN * 128];      // per-layer linear output
__device__ float g_agg1[NN * 128];
__device__ float g_agg2[NN * 128];
__device__ float g_dis[NN];          // (deg)^-1/2
__device__ float g_dinv[NN];         // (deg)^-1
__device__ int   g_degi[NN];         // in-degree (without self loop)
__device__ int   g_start[NN + 1];    // CSR offsets
__device__ int   g_cursor[NN];
__device__ int2  g_adj[EE];          // (src, coef bits)

// ---------------------------------------------------------------------------
__global__ void k_count(const int* __restrict__ dst, int* degi, int e) {
    int i = blockIdx.x * blockDim.x + threadIdx.x;
    if (i < e) atomicAdd(&degi[dst[i]], 1);
}

// single-block scan over N degrees; also emits dis/dinv (deg includes +1 self)
__global__ void __launch_bounds__(1024) k_scan(
    const int* __restrict__ degi, int* start, int* cursor,
    float* dis, float* dinv, int n)
{
    const int T = 1024;
    int tid = threadIdx.x;
    int chunk = (n + T - 1) / T;
    int lo = tid * chunk;
    int hi = min(lo + chunk, n);

    int sum = 0;
    for (int i = lo; i < hi; i++) sum += degi[i];

    __shared__ int ssum[T];
    ssum[tid] = sum;
    __syncthreads();
    for (int off = 1; off < T; off *= 2) {
        int v = (tid >= off) ? ssum[tid - off] : 0;
        __syncthreads();
        ssum[tid] += v;
        __syncthreads();
    }
    int run = (tid == 0) ? 0 : ssum[tid - 1];
    for (int i = lo; i < hi; i++) {
        int d = degi[i];
        start[i]  = run;
        cursor[i] = run;
        float df = (float)(d + 1);
        dis[i]  = rsqrtf(df);
        dinv[i] = 1.0f / df;
        run += d;
    }
    if (tid == T - 1) start[n] = ssum[T - 1];
}

__global__ void k_fill(const int* __restrict__ src, const int* __restrict__ dst,
                       const float* __restrict__ dis, int* cursor, int2* adj, int e)
{
    int i = blockIdx.x * blockDim.x + threadIdx.x;
    if (i >= e) return;
    int s = src[i], d = dst[i];
    int pos = atomicAdd(&cursor[d], 1);
    adj[pos] = make_int2(s, __float_as_int(dis[s] * dis[d]));
}

// ---------------------------------------------------------------------------
// GEMM: H[nrows,C] = act(X)[nrows,128] @ W[128,C]
// AGG = H*dinv + bias (self-loop + bias).  128-row block tile, 8x(C/16) micro.
// ---------------------------------------------------------------------------
template <int C, bool RELU>
__global__ void __launch_bounds__(256) k_gemm(
    const float* __restrict__ X, const float* __restrict__ W,
    const float* __restrict__ bias, const float* __restrict__ dinv,
    float* __restrict__ H, float* __restrict__ AGG, int nrows)
{
    constexpr int MT = 128;          // rows per block
    constexpr int KT = 16;           // k tile
    constexpr int NR = C / 16;       // cols per thread (8 or 4)
    constexpr int PAD = 4;

    __shared__ __align__(16) float Xs[KT][MT + PAD];  // k-major
    __shared__ __align__(16) float Ws[KT][C];

    const int t  = threadIdx.x;
    const int cx = t % 16;           // col group
    const int ry = t / 16;           // row group (0..15) -> 8 rows each
    const int m0 = blockIdx.x * MT;

    float acc[8][NR] = {};

    for (int k0 = 0; k0 < 128; k0 += KT) {
        // X tile: MT*KT floats = 512 float4, 2 per thread; transpose to k-major
        #pragma unroll
        for (int l = 0; l < 2; l++) {
            int idx = t + l * 256;
            int row = idx / 4;       // KT/4 = 4 float4 per row
            int j   = idx % 4;
            float4 v = make_float4(0.f, 0.f, 0.f, 0.f);
            if (m0 + row < nrows)
                v = *(const float4*)&X[(m0 + row) * 128 + k0 + j * 4];
            if (RELU) {
                v.x = fmaxf(v.x, 0.f); v.y = fmaxf(v.y, 0.f);
                v.z = fmaxf(v.z, 0.f); v.w = fmaxf(v.w, 0.f);
            }
            Xs[j * 4 + 0][row] = v.x;
            Xs[j * 4 + 1][row] = v.y;
            Xs[j * 4 + 2][row] = v.z;
            Xs[j * 4 + 3][row] = v.w;
        }
        // W tile: KT*C floats
        #pragma unroll
        for (int l = 0; l < (KT * C / 4) / 256; l++) {
            int idx = t + l * 256;
            int k   = idx / (C / 4);
            int cq  = idx % (C / 4);
            *(float4*)&Ws[k][cq * 4] = *(const float4*)&W[(k0 + k) * C + cq * 4];
        }
        __syncthreads();

        #pragma unroll
        for (int k = 0; k < KT; k++) {
            float xr[8], wr[NR];
            *(float4*)&xr[0] = *(const float4*)&Xs[k][ry * 8];
            *(float4*)&xr[4] = *(const float4*)&Xs[k][ry * 8 + 4];
            #pragma unroll
            for (int q = 0; q < NR / 4; q++)
                *(float4*)&wr[q * 4] = *(const float4*)&Ws[k][cx * NR + q * 4];
            #pragma unroll
            for (int i = 0; i < 8; i++)
                #pragma unroll
                for (int j = 0; j < NR; j++)
                    acc[i][j] = fmaf(xr[i], wr[j], acc[i][j]);
        }
        __syncthreads();
    }

    float bv[NR];
    #pragma unroll
    for (int q = 0; q < NR / 4; q++)
        *(float4*)&bv[q * 4] = *(const float4*)&bias[cx * NR + q * 4];

    #pragma unroll
    for (int i = 0; i < 8; i++) {
        int row = m0 + ry * 8 + i;
        if (row < nrows) {
            float di = dinv[row];
            #pragma unroll
            for (int q = 0; q < NR / 4; q++) {
                float4 hv = make_float4(acc[i][q*4+0], acc[i][q*4+1],
                                        acc[i][q*4+2], acc[i][q*4+3]);
                *(float4*)&H[row * C + cx * NR + q * 4] = hv;
                float4 av = make_float4(fmaf(hv.x, di, bv[q*4+0]),
                                        fmaf(hv.y, di, bv[q*4+1]),
                                        fmaf(hv.z, di, bv[q*4+2]),
                                        fmaf(hv.w, di, bv[q*4+3]));
                *(float4*)&AGG[row * C + cx * NR + q * 4] = av;
            }
        }
    }
}

// ---------------------------------------------------------------------------
// CSR gather:  AGG[d] += sum_{e in in(d)} H[src_e] * coef_e
// C/4 lanes per node (float4 per lane); no atomics.
// ---------------------------------------------------------------------------
template <int C>
__global__ void __launch_bounds__(256) k_gather(
    const int* __restrict__ start, const int2* __restrict__ adj,
    const float* __restrict__ H, float* __restrict__ AGG, int n)
{
    constexpr int LPN = C / 4;       // lanes per node
    constexpr int NPW = 32 / LPN;    // nodes per warp
    int warp = (blockIdx.x * blockDim.x + threadIdx.x) >> 5;
    int lane = threadIdx.x & 31;
    int node = warp * NPW + lane / LPN;
    int cl   = lane % LPN;
    if (node >= n) return;

    int s0 = start[node];
    int s1 = start[node + 1];

    float4 acc = *(const float4*)&AGG[node * C + cl * 4];

    int i = s0;
    for (; i + 1 < s1; i += 2) {
        int2 a0 = adj[i];
        int2 a1 = adj[i + 1];
        float c0 = __int_as_float(a0.y);
        float c1 = __int_as_float(a1.y);
        float4 v0 = *(const float4*)&H[a0.x * C + cl * 4];
        float4 v1 = *(const float4*)&H[a1.x * C + cl * 4];
        acc.x = fmaf(v0.x, c0, fmaf(v1.x, c1, acc.x));
        acc.y = fmaf(v0.y, c0, fmaf(v1.y, c1, acc.y));
        acc.z = fmaf(v0.z, c0, fmaf(v1.z, c1, acc.z));
        acc.w = fmaf(v0.w, c0, fmaf(v1.w, c1, acc.w));
    }
    if (i < s1) {
        int2 a = adj[i];
        float c = __int_as_float(a.y);
        float4 v = *(const float4*)&H[a.x * C + cl * 4];
        acc.x = fmaf(v.x, c, acc.x);
        acc.y = fmaf(v.y, c, acc.y);
        acc.z = fmaf(v.z, c, acc.z);
        acc.w = fmaf(v.w, c, acc.w);
    }
    *(float4*)&AGG[node * C + cl * 4] = acc;
}

// ---------------------------------------------------------------------------
extern "C" void kernel_launch(void* const* d_in, const int* in_sizes, int n_in,
                              void* d_out, int out_size)
{
    const float* x  = (const float*)d_in[0];
    const int*   ei = (const int*)d_in[1];
    const float* W1 = (const float*)d_in[2];
    const float* b1 = (const float*)d_in[3];
    const float* W2 = (const float*)d_in[4];
    const float* b2 = (const float*)d_in[5];
    const float* W3 = (const float*)d_in[6];
    const float* b3 = (const float*)d_in[7];
    float* out = (float*)d_out;

    const int E = in_sizes[1] / 2;
    const int N = in_sizes[0] / 128;
    const int* src = ei;
    const int* dst = ei + E;

    float *ph, *pa1, *pa2, *pdis, *pdinv;
    int *pdegi, *pstart, *pcursor;
    int2 *padj;
    cudaGetSymbolAddress((void**)&ph,      g_h);
    cudaGetSymbolAddress((void**)&pa1,     g_agg1);
    cudaGetSymbolAddress((void**)&pa2,     g_agg2);
    cudaGetSymbolAddress((void**)&pdis,    g_dis);
    cudaGetSymbolAddress((void**)&pdinv,   g_dinv);
    cudaGetSymbolAddress((void**)&pdegi,   g_degi);
    cudaGetSymbolAddress((void**)&pstart,  g_start);
    cudaGetSymbolAddress((void**)&pcursor, g_cursor);
    cudaGetSymbolAddress((void**)&padj,    g_adj);

    // CSR build
    cudaMemsetAsync(pdegi, 0, N * sizeof(int));
    k_count<<<(E + 255) / 256, 256>>>(dst, pdegi, E);
    k_scan<<<1, 1024>>>(pdegi, pstart, pcursor, pdis, pdinv, N);
    k_fill<<<(E + 255) / 256, 256>>>(src, dst, pdis, pcursor, padj, E);

    const int gemm_blocks = (N + 127) / 128;
    const int gat128 = (N * 32 + 255) / 256;      // 1 node per warp
    const int gat64  = (N * 16 + 255) / 256;      // 2 nodes per warp

    // layer 1
    k_gemm<128, false><<<gemm_blocks, 256>>>(x, W1, b1, pdinv, ph, pa1, N);
    k_gather<128><<<gat128, 256>>>(pstart, padj, ph, pa1, N);
    // layer 2
    k_gemm<128, true><<<gemm_blocks, 256>>>(pa1, W2, b2, pdinv, ph, pa2, N);
    k_gather<128><<<gat128, 256>>>(pstart, padj, ph, pa2, N);
    // layer 3 (C=64)
    k_gemm<64, true><<<gemm_blocks, 256>>>(pa2, W3, b3, pdinv, ph, out, N);
    k_gather<64><<<gat64, 256>>>(pstart, padj, ph, out, N);
}